// round 4
// baseline (speedup 1.0000x reference)
#include <cuda_runtime.h>
#include <cuda_bf16.h>
#include <cstdint>

#define Bsz 4
#define Sq  2048
#define Dm  1024
#define Hh  16
#define Dh  64
#define Tt  (Bsz * Sq)   /* 8192 tokens */

// ---------------------------------------------------------------------------
// Scratch (__device__ globals; allocation-free per harness rules)
// ---------------------------------------------------------------------------
__device__ float g_Q[(size_t)Tt * Dm];
__device__ float g_K[(size_t)Tt * Dm];
__device__ float g_V[(size_t)Tt * Dm];
__device__ float g_Z[(size_t)Tt * Dm];

// bf16 split-precision staging
__device__ __nv_bfloat16 g_xh[(size_t)Tt * Dm];
__device__ __nv_bfloat16 g_xl[(size_t)Tt * Dm];
__device__ __nv_bfloat16 g_zh[(size_t)Tt * Dm];
__device__ __nv_bfloat16 g_zl[(size_t)Tt * Dm];
__device__ __nv_bfloat16 g_wh[(size_t)3 * Dm * Dm];  // QKV weights, [n=3072][k=1024]
__device__ __nv_bfloat16 g_wl[(size_t)3 * Dm * Dm];
__device__ __nv_bfloat16 g_oh[(size_t)Dm * Dm];      // W_O transposed, [n=1024][k=1024]
__device__ __nv_bfloat16 g_ol[(size_t)Dm * Dm];

// ---------------------------------------------------------------------------
// PTX helpers — ONLY arch-stable features (mma.sync sm_80, ldmatrix sm_75,
// cp.async sm_80). No tcgen05/TMA: harness PTX target is sm_103 (no 'a').
// ---------------------------------------------------------------------------
__device__ __forceinline__ uint32_t smem_u32(const void* p) {
    uint32_t a;
    asm("{ .reg .u64 t; cvta.to.shared.u64 t, %1; cvt.u32.u64 %0, t; }" : "=r"(a) : "l"(p));
    return a;
}
#define CP_ASYNC16(dst, src) \
    asm volatile("cp.async.cg.shared.global [%0], [%1], 16;" :: "r"(dst), "l"(src))
#define CP_COMMIT() asm volatile("cp.async.commit_group;" ::: "memory")
#define CP_WAIT1()  asm volatile("cp.async.wait_group 1;" ::: "memory")
#define CP_WAIT0()  asm volatile("cp.async.wait_group 0;" ::: "memory")

__device__ __forceinline__ void ldmat4(uint32_t r[4], uint32_t addr) {
    asm volatile("ldmatrix.sync.aligned.m8n8.x4.shared.b16 {%0,%1,%2,%3}, [%4];"
                 : "=r"(r[0]), "=r"(r[1]), "=r"(r[2]), "=r"(r[3]) : "r"(addr));
}
__device__ __forceinline__ void mma16816(float* c, const uint32_t* a,
                                         uint32_t b0, uint32_t b1) {
    asm volatile("mma.sync.aligned.m16n8k16.row.col.f32.bf16.bf16.f32 "
                 "{%0,%1,%2,%3}, {%4,%5,%6,%7}, {%8,%9}, {%0,%1,%2,%3};"
                 : "+f"(c[0]), "+f"(c[1]), "+f"(c[2]), "+f"(c[3])
                 : "r"(a[0]), "r"(a[1]), "r"(a[2]), "r"(a[3]), "r"(b0), "r"(b1));
}

// ---------------------------------------------------------------------------
// Prep: split fp32 -> bf16 hi/lo
// ---------------------------------------------------------------------------
__global__ void conv_split(const float* __restrict__ in, __nv_bfloat16* __restrict__ hi,
                           __nv_bfloat16* __restrict__ lo, int n4)
{
    int i = blockIdx.x * blockDim.x + threadIdx.x;
    if (i >= n4) return;
    float4 v = ((const float4*)in)[i];
    __nv_bfloat16 h0 = __float2bfloat16(v.x), h1 = __float2bfloat16(v.y);
    __nv_bfloat16 h2 = __float2bfloat16(v.z), h3 = __float2bfloat16(v.w);
    __nv_bfloat16 l0 = __float2bfloat16(v.x - __bfloat162float(h0));
    __nv_bfloat16 l1 = __float2bfloat16(v.y - __bfloat162float(h1));
    __nv_bfloat16 l2 = __float2bfloat16(v.z - __bfloat162float(h2));
    __nv_bfloat16 l3 = __float2bfloat16(v.w - __bfloat162float(h3));
    ((__nv_bfloat162*)hi)[2 * i]     = __nv_bfloat162(h0, h1);
    ((__nv_bfloat162*)hi)[2 * i + 1] = __nv_bfloat162(h2, h3);
    ((__nv_bfloat162*)lo)[2 * i]     = __nv_bfloat162(l0, l1);
    ((__nv_bfloat162*)lo)[2 * i + 1] = __nv_bfloat162(l2, l3);
}

// QKV weights -> [n=3072][k=1024] bf16 hi/lo, n = proj*1024 + h*64 + e, k = d
__global__ void conv_wqkv(const float* __restrict__ wq, const float* __restrict__ wk,
                          const float* __restrict__ wv)
{
    int id = blockIdx.x * 256 + threadIdx.x;
    if (id >= 3 * Dm * Dm) return;
    int n = id >> 10, d = id & 1023;
    int proj = n >> 10, nl = n & 1023, h = nl >> 6, e = nl & 63;
    const float* W = (proj == 0 ? wq : proj == 1 ? wk : wv);
    float v = W[((size_t)h * Dm + d) * Dh + e];
    __nv_bfloat16 hh = __float2bfloat16(v);
    g_wh[id] = hh;
    g_wl[id] = __float2bfloat16(v - __bfloat162float(hh));
}

// W_O (H, DH, D) -> [n=d_out][k=h*64+e] bf16 hi/lo
__global__ void conv_wo(const float* __restrict__ wo)
{
    int id = blockIdx.x * 256 + threadIdx.x;
    if (id >= Dm * Dm) return;
    int n = id >> 10, k = id & 1023;
    float v = wo[(size_t)k * Dm + n];
    __nv_bfloat16 hh = __float2bfloat16(v);
    g_oh[id] = hh;
    g_ol[id] = __float2bfloat16(v - __bfloat162float(hh));
}

// ---------------------------------------------------------------------------
// HMMA bf16x3 GEMM: C[m][n] = sum_k A[m][k]*B[n][k] + bias[n]
// CTA tile 128x128x32, 8 warps (2x4), warp tile 64x32.
// Smem: tile-contiguous (each 8x8 bf16 tile = 128 contiguous bytes) so
// ldmatrix.x4 reads are conflict-free. Double buffered via cp.async.
// grid = (M/128, N/128). For QKV, N-tile selects proj via n0>>10.
// ---------------------------------------------------------------------------
#define ARR_BYTES 8192                 /* 128x32 bf16 */
#define BUF_BYTES (4 * ARR_BYTES)      /* Ah, Al, Bh, Bl */
#define GEMM_SMEM (2 * BUF_BYTES)      /* 65536 */

__global__ __launch_bounds__(256) void hmma_gemm(
    const __nv_bfloat16* __restrict__ Ah, const __nv_bfloat16* __restrict__ Al,
    const __nv_bfloat16* __restrict__ Bh, const __nv_bfloat16* __restrict__ Bl,
    const float* __restrict__ b0, const float* __restrict__ b1,
    const float* __restrict__ b2,
    float* __restrict__ C0, float* __restrict__ C1, float* __restrict__ C2)
{
    extern __shared__ char smc[];
    const uint32_t sb = smem_u32(smc);
    const int tid = threadIdx.x, wid = tid >> 5, lane = tid & 31;
    const int warp_m = wid >> 2, warp_n = wid & 3;
    const int g = lane >> 3, r = lane & 7;
    const int m0  = blockIdx.x * 128;
    const int n0g = blockIdx.y * 128;
    const int proj = n0g >> 10;
    const int nl   = n0g & 1023;
    const float* bias = (proj == 0 ? b0 : proj == 1 ? b1 : b2);
    float* C = (proj == 0 ? C0 : proj == 1 ? C1 : C2);

    const __nv_bfloat16* srcs[4];
    srcs[0] = Ah + (size_t)m0  * Dm;
    srcs[1] = Al + (size_t)m0  * Dm;
    srcs[2] = Bh + (size_t)n0g * Dm;
    srcs[3] = Bl + (size_t)n0g * Dm;

    // per-lane ldmatrix address constants (tile-contiguous layout)
    // A frag (mi, ks): off = ((warp_m*8 + mi*2 + (g&1))*4 + 2*ks + (g>>1))*128 + r*16
    // B frag (np, ks): off = ((warp_n*4 + np*2 + (g>>1))*4 + 2*ks + (g&1))*128 + r*16
    const uint32_t aoff0 = (uint32_t)(((warp_m * 8 + (g & 1)) * 4 + (g >> 1)) * 128 + r * 16);
    const uint32_t boff0 = (uint32_t)(((warp_n * 4 + (g >> 1)) * 4 + (g & 1)) * 128 + r * 16);

    auto fill = [&](int buf, int k0) {
        #pragma unroll
        for (int arr = 0; arr < 4; arr++) {
            uint32_t abase = sb + buf * BUF_BYTES + arr * ARR_BYTES;
            const __nv_bfloat16* s = srcs[arr];
            #pragma unroll
            for (int i = 0; i < 2; i++) {
                int cid = tid + 256 * i;
                int row = cid >> 2, kc = (cid & 3) * 8;
                const void* gsrc = s + (size_t)row * Dm + k0 + kc;
                uint32_t soff = abase + (uint32_t)(((row >> 3) * 4 + (kc >> 3)) * 128
                                                   + (row & 7) * 16);
                CP_ASYNC16(soff, gsrc);
            }
        }
    };

    float acc[4][4][4];
    #pragma unroll
    for (int mi = 0; mi < 4; mi++)
        #pragma unroll
        for (int nj = 0; nj < 4; nj++)
            #pragma unroll
            for (int c = 0; c < 4; c++) acc[mi][nj][c] = 0.f;

    fill(0, 0);
    CP_COMMIT();

    const int NIT = Dm / 32;   // 32 slabs
    for (int it = 0; it < NIT; it++) {
        if (it + 1 < NIT) { fill((it + 1) & 1, (it + 1) * 32); CP_COMMIT(); CP_WAIT1(); }
        else              { CP_WAIT0(); }
        __syncthreads();

        const uint32_t bufb = sb + (it & 1) * BUF_BYTES;
        const uint32_t bAh = bufb, bAl = bufb + ARR_BYTES;
        const uint32_t bBh = bufb + 2 * ARR_BYTES, bBl = bufb + 3 * ARR_BYTES;

        uint32_t afr[2][4][4];
        // ---- load Ah fragments (both k-steps, 4 m-tiles) ----
        #pragma unroll
        for (int ks = 0; ks < 2; ks++)
            #pragma unroll
            for (int mi = 0; mi < 4; mi++)
                ldmat4(afr[ks][mi], bAh + aoff0 + mi * 1024 + ks * 256);
        // ---- pass 1: Ah x Bh; pass 2: Ah x Bl ----
        #pragma unroll
        for (int pb = 0; pb < 2; pb++) {
            const uint32_t bB = pb ? bBl : bBh;
            #pragma unroll
            for (int ks = 0; ks < 2; ks++) {
                uint32_t bb[2][4];
                ldmat4(bb[0], bB + boff0 + ks * 256);
                ldmat4(bb[1], bB + boff0 + 1024 + ks * 256);
                #pragma unroll
                for (int mi = 0; mi < 4; mi++)
                    #pragma unroll
                    for (int nj = 0; nj < 4; nj++)
                        mma16816(acc[mi][nj], afr[ks][mi],
                                 bb[nj >> 1][(nj & 1) * 2], bb[nj >> 1][(nj & 1) * 2 + 1]);
            }
        }
        // ---- pass 3: Al x Bh ----
        #pragma unroll
        for (int ks = 0; ks < 2; ks++)
            #pragma unroll
            for (int mi = 0; mi < 4; mi++)
                ldmat4(afr[ks][mi], bAl + aoff0 + mi * 1024 + ks * 256);
        #pragma unroll
        for (int ks = 0; ks < 2; ks++) {
            uint32_t bb[2][4];
            ldmat4(bb[0], bBh + boff0 + ks * 256);
            ldmat4(bb[1], bBh + boff0 + 1024 + ks * 256);
            #pragma unroll
            for (int mi = 0; mi < 4; mi++)
                #pragma unroll
                for (int nj = 0; nj < 4; nj++)
                    mma16816(acc[mi][nj], afr[ks][mi],
                             bb[nj >> 1][(nj & 1) * 2], bb[nj >> 1][(nj & 1) * 2 + 1]);
        }
        __syncthreads();
    }

    // ---- epilogue: bias + direct fp32 stores ----
    const int gq = lane >> 2, tq = lane & 3;
    #pragma unroll
    for (int mi = 0; mi < 4; mi++) {
        const int row = m0 + warp_m * 64 + mi * 16 + gq;
        #pragma unroll
        for (int nj = 0; nj < 4; nj++) {
            const int col = nl + warp_n * 32 + nj * 8 + tq * 2;
            const float bv0 = bias[col], bv1 = bias[col + 1];
            float2 v0 = make_float2(acc[mi][nj][0] + bv0, acc[mi][nj][1] + bv1);
            float2 v1 = make_float2(acc[mi][nj][2] + bv0, acc[mi][nj][3] + bv1);
            *(float2*)(C + (size_t)row * Dm + col)       = v0;
            *(float2*)(C + (size_t)(row + 8) * Dm + col) = v1;
        }
    }
}

// ---------------------------------------------------------------------------
// Flash attention (SIMT fp32, unchanged from passing round)
// ---------------------------------------------------------------------------
__global__ __launch_bounds__(256) void attn_kernel()
{
    extern __shared__ float sm[];
    float (*Qt)[64] = (float (*)[64])(sm);
    float (*Kt)[64] = (float (*)[64])(sm + 64 * 64);
    float (*Vs)[64] = (float (*)[64])(sm + 2 * 64 * 64);
    float (*Ps)[64] = (float (*)[64])(sm + 3 * 64 * 64);

    const int qb = blockIdx.x, h = blockIdx.y, b = blockIdx.z;
    const int tid = threadIdx.x;
    const int tx = tid & 15, ty = tid >> 4;
    const int lr = tid >> 2;
    const int le = (tid & 3) * 16;

    const float* Qg = g_Q + (size_t)(b * Sq + qb * 64) * Dm + h * Dh;
    #pragma unroll
    for (int i = 0; i < 4; i++) {
        float4 v = *(const float4*)(Qg + (size_t)lr * Dm + le + i * 4);
        Qt[le + i * 4 + 0][lr] = v.x * 0.125f;
        Qt[le + i * 4 + 1][lr] = v.y * 0.125f;
        Qt[le + i * 4 + 2][lr] = v.z * 0.125f;
        Qt[le + i * 4 + 3][lr] = v.w * 0.125f;
    }

    float o[4][4];
    float m[4], l[4];
    #pragma unroll
    for (int r = 0; r < 4; r++) {
        m[r] = -1e30f; l[r] = 0.f;
        #pragma unroll
        for (int c = 0; c < 4; c++) o[r][c] = 0.f;
    }

    for (int kt = 0; kt <= qb; kt++) {
        __syncthreads();
        const float* Kg = g_K + (size_t)(b * Sq + kt * 64) * Dm + h * Dh;
        const float* Vg = g_V + (size_t)(b * Sq + kt * 64) * Dm + h * Dh;
        #pragma unroll
        for (int i = 0; i < 4; i++) {
            float4 v = *(const float4*)(Kg + (size_t)lr * Dm + le + i * 4);
            Kt[le + i * 4 + 0][lr] = v.x;
            Kt[le + i * 4 + 1][lr] = v.y;
            Kt[le + i * 4 + 2][lr] = v.z;
            Kt[le + i * 4 + 3][lr] = v.w;
            float4 w = *(const float4*)(Vg + (size_t)lr * Dm + le + i * 4);
            *(float4*)&Vs[lr][le + i * 4] = w;
        }
        __syncthreads();

        float s[4][4];
        #pragma unroll
        for (int r = 0; r < 4; r++)
            #pragma unroll
            for (int c = 0; c < 4; c++) s[r][c] = 0.f;
        #pragma unroll 8
        for (int e = 0; e < 64; e++) {
            float a[4], k4[4];
            *(float4*)a  = *(const float4*)&Qt[e][ty * 4];
            *(float4*)k4 = *(const float4*)&Kt[e][tx * 4];
            #pragma unroll
            for (int r = 0; r < 4; r++)
                #pragma unroll
                for (int c = 0; c < 4; c++)
                    s[r][c] += a[r] * k4[c];
        }

        if (kt == qb) {
            #pragma unroll
            for (int r = 0; r < 4; r++)
                #pragma unroll
                for (int c = 0; c < 4; c++)
                    if (tx * 4 + c > ty * 4 + r) s[r][c] = -1e30f;
        }

        float rmax[4], rsum[4];
        #pragma unroll
        for (int r = 0; r < 4; r++)
            rmax[r] = fmaxf(fmaxf(s[r][0], s[r][1]), fmaxf(s[r][2], s[r][3]));
        #pragma unroll
        for (int off = 1; off < 16; off <<= 1)
            #pragma unroll
            for (int r = 0; r < 4; r++)
                rmax[r] = fmaxf(rmax[r], __shfl_xor_sync(0xffffffffu, rmax[r], off));

        #pragma unroll
        for (int r = 0; r < 4; r++) {
            float mn = fmaxf(m[r], rmax[r]);
            float sc = __expf(m[r] - mn);
            m[r] = mn;
            #pragma unroll
            for (int c = 0; c < 4; c++) s[r][c] = __expf(s[r][c] - mn);
            rsum[r] = (s[r][0] + s[r][1]) + (s[r][2] + s[r][3]);
            l[r] *= sc;
            #pragma unroll
            for (int c = 0; c < 4; c++) o[r][c] *= sc;
        }
        #pragma unroll
        for (int off = 1; off < 16; off <<= 1)
            #pragma unroll
            for (int r = 0; r < 4; r++)
                rsum[r] += __shfl_xor_sync(0xffffffffu, rsum[r], off);
        #pragma unroll
        for (int r = 0; r < 4; r++) l[r] += rsum[r];

        #pragma unroll
        for (int r = 0; r < 4; r++)
            *(float4*)&Ps[ty * 4 + r][tx * 4] =
                make_float4(s[r][0], s[r][1], s[r][2], s[r][3]);
        __syncthreads();

        #pragma unroll 4
        for (int k0 = 0; k0 < 64; k0 += 4) {
            float p[4][4];
            #pragma unroll
            for (int r = 0; r < 4; r++)
                *(float4*)p[r] = *(const float4*)&Ps[ty * 4 + r][k0];
            #pragma unroll
            for (int kk = 0; kk < 4; kk++) {
                float v4[4];
                *(float4*)v4 = *(const float4*)&Vs[k0 + kk][tx * 4];
                #pragma unroll
                for (int r = 0; r < 4; r++)
                    #pragma unroll
                    for (int c = 0; c < 4; c++)
                        o[r][c] += p[r][kk] * v4[c];
            }
        }
    }

    float* Zg = g_Z + (size_t)(b * Sq + qb * 64) * Dm + h * Dh;
    #pragma unroll
    for (int r = 0; r < 4; r++) {
        float inv = 1.f / l[r];
        float4 v = make_float4(o[r][0] * inv, o[r][1] * inv,
                               o[r][2] * inv, o[r][3] * inv);
        *(float4*)(Zg + (size_t)(ty * 4 + r) * Dm + tx * 4) = v;
    }
}

// ---------------------------------------------------------------------------
extern "C" void kernel_launch(void* const* d_in, const int* in_sizes, int n_in,
                              void* d_out, int out_size)
{
    const float* x  = (const float*)d_in[0];
    const float* wq = (const float*)d_in[1];
    const float* bq = (const float*)d_in[2];
    const float* wk = (const float*)d_in[3];
    const float* bk = (const float*)d_in[4];
    const float* wv = (const float*)d_in[5];
    const float* bv = (const float*)d_in[6];
    const float* wo = (const float*)d_in[7];
    const float* bo = (const float*)d_in[8];
    float* out = (float*)d_out;

    cudaFuncSetAttribute(attn_kernel,
                         cudaFuncAttributeMaxDynamicSharedMemorySize, 65536);
    cudaFuncSetAttribute(hmma_gemm,
                         cudaFuncAttributeMaxDynamicSharedMemorySize, GEMM_SMEM);

    void* p;
    cudaGetSymbolAddress(&p, g_xh); __nv_bfloat16* xh = (__nv_bfloat16*)p;
    cudaGetSymbolAddress(&p, g_xl); __nv_bfloat16* xl = (__nv_bfloat16*)p;
    cudaGetSymbolAddress(&p, g_zh); __nv_bfloat16* zh = (__nv_bfloat16*)p;
    cudaGetSymbolAddress(&p, g_zl); __nv_bfloat16* zl = (__nv_bfloat16*)p;
    cudaGetSymbolAddress(&p, g_wh); __nv_bfloat16* wh = (__nv_bfloat16*)p;
    cudaGetSymbolAddress(&p, g_wl); __nv_bfloat16* wl = (__nv_bfloat16*)p;
    cudaGetSymbolAddress(&p, g_oh); __nv_bfloat16* oh = (__nv_bfloat16*)p;
    cudaGetSymbolAddress(&p, g_ol); __nv_bfloat16* ol = (__nv_bfloat16*)p;
    cudaGetSymbolAddress(&p, g_Q);  float* Qf = (float*)p;
    cudaGetSymbolAddress(&p, g_K);  float* Kf = (float*)p;
    cudaGetSymbolAddress(&p, g_V);  float* Vf = (float*)p;
    cudaGetSymbolAddress(&p, g_Z);  float* Zf = (float*)p;

    // 1. split x, transpose+split weights
    conv_split<<<(Tt * Dm / 4 + 255) / 256, 256>>>(x, xh, xl, Tt * Dm / 4);
    conv_wqkv<<<(3 * Dm * Dm + 255) / 256, 256>>>(wq, wk, wv);
    conv_wo<<<(Dm * Dm + 255) / 256, 256>>>(wo);

    // 2. QKV projection: [8192 x 1024] * [3072 x 1024]^T -> Q|K|V fp32
    hmma_gemm<<<dim3(Tt / 128, 24), 256, GEMM_SMEM>>>(
        xh, xl, wh, wl, bq, bk, bv, Qf, Kf, Vf);

    // 3. attention (SIMT fp32)
    attn_kernel<<<dim3(Sq / 64, Hh, Bsz), 256, 65536>>>();

    // 4. split z, output projection
    conv_split<<<(Tt * Dm / 4 + 255) / 256, 256>>>(Zf, zh, zl, Tt * Dm / 4);
    hmma_gemm<<<dim3(Tt / 128, 8), 256, GEMM_SMEM>>>(
        zh, zl, oh, ol, bo, bo, bo, out, out, out);
}

// round 5
// speedup vs baseline: 1.5394x; 1.5394x over previous
#include <cuda_runtime.h>
#include <cuda_bf16.h>
#include <cstdint>

#define Bsz 4
#define Sq  2048
#define Dm  1024
#define Hh  16
#define Dh  64
#define Tt  (Bsz * Sq)

// ---------------- scratch ----------------
__device__ __nv_bfloat16 g_xh[(size_t)Tt * Dm];
__device__ __nv_bfloat16 g_xl[(size_t)Tt * Dm];
__device__ __nv_bfloat16 g_wh[(size_t)3 * Dm * Dm];
__device__ __nv_bfloat16 g_wl[(size_t)3 * Dm * Dm];
__device__ __nv_bfloat16 g_oh[(size_t)Dm * Dm];
__device__ __nv_bfloat16 g_ol[(size_t)Dm * Dm];
__device__ __nv_bfloat16 g_qh[(size_t)Tt * Dm];
__device__ __nv_bfloat16 g_ql[(size_t)Tt * Dm];
__device__ __nv_bfloat16 g_kh[(size_t)Tt * Dm];
__device__ __nv_bfloat16 g_kl[(size_t)Tt * Dm];
__device__ __nv_bfloat16 g_vh[(size_t)Tt * Dm];
__device__ __nv_bfloat16 g_vl[(size_t)Tt * Dm];
__device__ __nv_bfloat16 g_zh[(size_t)Tt * Dm];
__device__ __nv_bfloat16 g_zl[(size_t)Tt * Dm];

// ---------------- helpers (arch-stable PTX only) ----------------
__device__ __forceinline__ uint32_t smem_u32(const void* p) {
    uint32_t a;
    asm("{ .reg .u64 t; cvta.to.shared.u64 t, %1; cvt.u32.u64 %0, t; }" : "=r"(a) : "l"(p));
    return a;
}
#define CP_ASYNC16(dst, src) \
    asm volatile("cp.async.cg.shared.global [%0], [%1], 16;" :: "r"(dst), "l"(src))
#define CP_COMMIT() asm volatile("cp.async.commit_group;" ::: "memory")
#define CP_WAIT1()  asm volatile("cp.async.wait_group 1;" ::: "memory")
#define CP_WAIT0()  asm volatile("cp.async.wait_group 0;" ::: "memory")

__device__ __forceinline__ void ldmat4(uint32_t r[4], uint32_t a) {
    asm volatile("ldmatrix.sync.aligned.m8n8.x4.shared.b16 {%0,%1,%2,%3}, [%4];"
                 : "=r"(r[0]), "=r"(r[1]), "=r"(r[2]), "=r"(r[3]) : "r"(a));
}
__device__ __forceinline__ void ldmat4t(uint32_t r[4], uint32_t a) {
    asm volatile("ldmatrix.sync.aligned.m8n8.x4.trans.shared.b16 {%0,%1,%2,%3}, [%4];"
                 : "=r"(r[0]), "=r"(r[1]), "=r"(r[2]), "=r"(r[3]) : "r"(a));
}
__device__ __forceinline__ void mma16816(float* c, const uint32_t* a,
                                         uint32_t b0, uint32_t b1) {
    asm volatile("mma.sync.aligned.m16n8k16.row.col.f32.bf16.bf16.f32 "
                 "{%0,%1,%2,%3}, {%4,%5,%6,%7}, {%8,%9}, {%0,%1,%2,%3};"
                 : "+f"(c[0]), "+f"(c[1]), "+f"(c[2]), "+f"(c[3])
                 : "r"(a[0]), "r"(a[1]), "r"(a[2]), "r"(a[3]), "r"(b0), "r"(b1));
}
#define CVT2(res, hi, lo) \
    asm("cvt.rn.bf16x2.f32 %0, %1, %2;" : "=r"(res) : "f"(hi), "f"(lo))

// fast exp on fma/alu pipes (x <= 0, clamped; ~1e-7 rel err)
__device__ __forceinline__ float fexp(float x) {
    x = fmaxf(x, -80.f);
    float t = x * 1.44269504f;
    float fk = t + 12582912.f;
    int   i  = __float_as_int(fk) - 0x4B400000;
    float f  = t - (fk - 12582912.f);
    float p = 1.33978e-3f;
    p = fmaf(p, f, 9.67839e-3f);
    p = fmaf(p, f, 5.55041e-2f);
    p = fmaf(p, f, 2.40227e-1f);
    p = fmaf(p, f, 6.93147e-1f);
    p = fmaf(p, f, 1.0f);
    return __int_as_float(__float_as_int(p) + (i << 23));
}
// pack 2 floats -> bf16x2 hi + residual bf16x2 lo
__device__ __forceinline__ void pack_pair(uint32_t& hv, uint32_t& lv, float v0, float v1) {
    CVT2(hv, v1, v0);
    float f0 = __uint_as_float(hv << 16);
    float f1 = __uint_as_float(hv & 0xFFFF0000u);
    CVT2(lv, v1 - f1, v0 - f0);
}
__device__ __forceinline__ void split_store(__nv_bfloat16* H, __nv_bfloat16* L,
                                            size_t idx, float v0, float v1) {
    uint32_t hv, lv;
    pack_pair(hv, lv, v0, v1);
    *(uint32_t*)(H + idx) = hv;
    *(uint32_t*)(L + idx) = lv;
}

// ---------------- prep ----------------
__global__ void conv_split(const float* __restrict__ in, __nv_bfloat16* __restrict__ hi,
                           __nv_bfloat16* __restrict__ lo, int n4)
{
    int i = blockIdx.x * blockDim.x + threadIdx.x;
    if (i >= n4) return;
    float4 v = ((const float4*)in)[i];
    uint32_t h0, h1, l0, l1;
    pack_pair(h0, l0, v.x, v.y);
    pack_pair(h1, l1, v.z, v.w);
    ((uint32_t*)hi)[2 * i] = h0; ((uint32_t*)hi)[2 * i + 1] = h1;
    ((uint32_t*)lo)[2 * i] = l0; ((uint32_t*)lo)[2 * i + 1] = l1;
}
__global__ void conv_wqkv(const float* __restrict__ wq, const float* __restrict__ wk,
                          const float* __restrict__ wv)
{
    int id = blockIdx.x * 256 + threadIdx.x;
    if (id >= 3 * Dm * Dm) return;
    int n = id >> 10, d = id & 1023;
    int proj = n >> 10, nl = n & 1023, h = nl >> 6, e = nl & 63;
    const float* W = (proj == 0 ? wq : proj == 1 ? wk : wv);
    float v = W[((size_t)h * Dm + d) * Dh + e];
    __nv_bfloat16 hh = __float2bfloat16(v);
    g_wh[id] = hh;
    g_wl[id] = __float2bfloat16(v - __bfloat162float(hh));
}
__global__ void conv_wo(const float* __restrict__ wo)
{
    int id = blockIdx.x * 256 + threadIdx.x;
    if (id >= Dm * Dm) return;
    int n = id >> 10, k = id & 1023;
    float v = wo[(size_t)k * Dm + n];
    __nv_bfloat16 hh = __float2bfloat16(v);
    g_oh[id] = hh;
    g_ol[id] = __float2bfloat16(v - __bfloat162float(hh));
}

// ---------------- bf16x3 HMMA GEMM (mainloop = proven R3 version) -----------
#define ARR_BYTES 8192
#define BUF_BYTES (4 * ARR_BYTES)
#define GEMM_SMEM (2 * BUF_BYTES)

__global__ __launch_bounds__(256) void hmma_gemm(
    const __nv_bfloat16* __restrict__ Ah, const __nv_bfloat16* __restrict__ Al,
    const __nv_bfloat16* __restrict__ Bh, const __nv_bfloat16* __restrict__ Bl,
    const float* __restrict__ b0, const float* __restrict__ b1,
    const float* __restrict__ b2, float* __restrict__ C, int mode)
{
    extern __shared__ char smc[];
    const uint32_t sb = smem_u32(smc);
    const int tid = threadIdx.x, wid = tid >> 5, lane = tid & 31;
    const int warp_m = wid >> 2, warp_n = wid & 3;
    const int g = lane >> 3, r = lane & 7;
    const int m0  = blockIdx.x * 128;
    const int n0g = blockIdx.y * 128;
    const int proj = n0g >> 10;
    const int nl   = n0g & 1023;
    const float* bias = (proj == 0 ? b0 : proj == 1 ? b1 : b2);

    const __nv_bfloat16* srcs[4];
    srcs[0] = Ah + (size_t)m0  * Dm;
    srcs[1] = Al + (size_t)m0  * Dm;
    srcs[2] = Bh + (size_t)n0g * Dm;
    srcs[3] = Bl + (size_t)n0g * Dm;

    const uint32_t aoff0 = (uint32_t)(((warp_m * 8 + (g & 1)) * 4 + (g >> 1)) * 128 + r * 16);
    const uint32_t boff0 = (uint32_t)(((warp_n * 4 + (g >> 1)) * 4 + (g & 1)) * 128 + r * 16);

    auto fill = [&](int buf, int k0) {
        #pragma unroll
        for (int arr = 0; arr < 4; arr++) {
            uint32_t abase = sb + buf * BUF_BYTES + arr * ARR_BYTES;
            const __nv_bfloat16* s = srcs[arr];
            #pragma unroll
            for (int i = 0; i < 2; i++) {
                int cid = tid + 256 * i;
                int row = cid >> 2, kc = (cid & 3) * 8;
                const void* gsrc = s + (size_t)row * Dm + k0 + kc;
                uint32_t soff = abase + (uint32_t)(((row >> 3) * 4 + (kc >> 3)) * 128
                                                   + (row & 7) * 16);
                CP_ASYNC16(soff, gsrc);
            }
        }
    };

    float acc[4][4][4];
    #pragma unroll
    for (int mi = 0; mi < 4; mi++)
        #pragma unroll
        for (int nj = 0; nj < 4; nj++)
            #pragma unroll
            for (int c = 0; c < 4; c++) acc[mi][nj][c] = 0.f;

    fill(0, 0);
    CP_COMMIT();

    const int NIT = Dm / 32;
    for (int it = 0; it < NIT; it++) {
        if (it + 1 < NIT) { fill((it + 1) & 1, (it + 1) * 32); CP_COMMIT(); CP_WAIT1(); }
        else              { CP_WAIT0(); }
        __syncthreads();

        const uint32_t bufb = sb + (it & 1) * BUF_BYTES;
        const uint32_t bAh = bufb, bAl = bufb + ARR_BYTES;
        const uint32_t bBh = bufb + 2 * ARR_BYTES, bBl = bufb + 3 * ARR_BYTES;

        uint32_t afr[2][4][4];
        #pragma unroll
        for (int ks = 0; ks < 2; ks++)
            #pragma unroll
            for (int mi = 0; mi < 4; mi++)
                ldmat4(afr[ks][mi], bAh + aoff0 + mi * 1024 + ks * 256);
        #pragma unroll
        for (int pb = 0; pb < 2; pb++) {
            const uint32_t bB = pb ? bBl : bBh;
            #pragma unroll
            for (int ks = 0; ks < 2; ks++) {
                uint32_t bb[2][4];
                ldmat4(bb[0], bB + boff0 + ks * 256);
                ldmat4(bb[1], bB + boff0 + 1024 + ks * 256);
                #pragma unroll
                for (int mi = 0; mi < 4; mi++)
                    #pragma unroll
                    for (int nj = 0; nj < 4; nj++)
                        mma16816(acc[mi][nj], afr[ks][mi],
                                 bb[nj >> 1][(nj & 1) * 2], bb[nj >> 1][(nj & 1) * 2 + 1]);
            }
        }
        #pragma unroll
        for (int ks = 0; ks < 2; ks++)
            #pragma unroll
            for (int mi = 0; mi < 4; mi++)
                ldmat4(afr[ks][mi], bAl + aoff0 + mi * 1024 + ks * 256);
        #pragma unroll
        for (int ks = 0; ks < 2; ks++) {
            uint32_t bb[2][4];
            ldmat4(bb[0], bBh + boff0 + ks * 256);
            ldmat4(bb[1], bBh + boff0 + 1024 + ks * 256);
            #pragma unroll
            for (int mi = 0; mi < 4; mi++)
                #pragma unroll
                for (int nj = 0; nj < 4; nj++)
                    mma16816(acc[mi][nj], afr[ks][mi],
                             bb[nj >> 1][(nj & 1) * 2], bb[nj >> 1][(nj & 1) * 2 + 1]);
        }
        __syncthreads();
    }

    // epilogue
    const int gq = lane >> 2, tq = lane & 3;
    if (mode == 0) {
        #pragma unroll
        for (int mi = 0; mi < 4; mi++) {
            const int row = m0 + warp_m * 64 + mi * 16 + gq;
            #pragma unroll
            for (int nj = 0; nj < 4; nj++) {
                const int col = nl + warp_n * 32 + nj * 8 + tq * 2;
                const float bv0 = bias[col], bv1 = bias[col + 1];
                *(float2*)(C + (size_t)row * Dm + col) =
                    make_float2(acc[mi][nj][0] + bv0, acc[mi][nj][1] + bv1);
                *(float2*)(C + (size_t)(row + 8) * Dm + col) =
                    make_float2(acc[mi][nj][2] + bv0, acc[mi][nj][3] + bv1);
            }
        }
    } else {
        __nv_bfloat16* H = (proj == 0 ? g_qh : proj == 1 ? g_kh : g_vh);
        __nv_bfloat16* L = (proj == 0 ? g_ql : proj == 1 ? g_kl : g_vl);
        const float sc = (proj == 0) ? 0.125f : 1.f;
        #pragma unroll
        for (int mi = 0; mi < 4; mi++) {
            const size_t row = (size_t)(m0 + warp_m * 64 + mi * 16 + gq);
            #pragma unroll
            for (int nj = 0; nj < 4; nj++) {
                const int col = nl + warp_n * 32 + nj * 8 + tq * 2;
                const float bv0 = bias[col], bv1 = bias[col + 1];
                split_store(H, L, row * Dm + col,
                            (acc[mi][nj][0] + bv0) * sc, (acc[mi][nj][1] + bv1) * sc);
                split_store(H, L, (row + 8) * Dm + col,
                            (acc[mi][nj][2] + bv0) * sc, (acc[mi][nj][3] + bv1) * sc);
            }
        }
    }
}

// ---------------- HMMA flash attention ----------------
// grid (Sq/128, Hh, Bsz), 256 thr. smem 64KB: stage s: Kh s*32768, Kl +8192,
// Vh +16384, Vl +24576. Q staged in [0,32768) before loop.
#define ATT_SMEM 65536
__device__ __forceinline__ uint32_t swo(int row, int e) {
    return (uint32_t)(((row >> 3) * 8 + (e >> 3)) * 128 + (((row & 7) ^ (e >> 3)) << 4));
}

__global__ __launch_bounds__(256) void fattn()
{
    extern __shared__ char sm[];
    const uint32_t sb = smem_u32(sm);
    const int tid = threadIdx.x, w = tid >> 5, lane = tid & 31;
    const int qb = blockIdx.x, h = blockIdx.y, b = blockIdx.z;
    const int q0 = qb * 128;
    const size_t tq0 = (size_t)b * Sq + q0;

    // stage Q (hi/lo) -> frags
    #pragma unroll
    for (int i = 0; i < 8; i++) {
        int sid = tid + 256 * i;
        int arr = sid >> 10, rc = sid & 1023, row = rc >> 3, c8 = rc & 7;
        const __nv_bfloat16* src = (arr ? g_ql : g_qh) + (tq0 + row) * Dm + h * 64 + c8 * 8;
        CP_ASYNC16(sb + arr * 16384 + (uint32_t)(((row >> 3) * 8 + c8) * 128
                   + (((row & 7) ^ c8) << 4)), src);
    }
    CP_COMMIT(); CP_WAIT0(); __syncthreads();

    uint32_t qh[4][4], ql[4][4];
    {
        int row = 16 * w + (lane & 7) + ((lane >> 3) & 1) * 8;
        #pragma unroll
        for (int ks = 0; ks < 4; ks++) {
            uint32_t off = swo(row, ks * 16 + (lane >> 4) * 8);
            ldmat4(qh[ks], sb + off);
            ldmat4(ql[ks], sb + 16384 + off);
        }
    }
    __syncthreads();

    float o[8][4], m[2] = {-1e30f, -1e30f}, l[2] = {0.f, 0.f};
    #pragma unroll
    for (int nj = 0; nj < 8; nj++)
        #pragma unroll
        for (int c = 0; c < 4; c++) o[nj][c] = 0.f;

    const int nkv = 2 * qb + 2;
    const size_t tb = (size_t)b * Sq;

    auto fillkv = [&](int st, int kt) {
        #pragma unroll
        for (int i = 0; i < 8; i++) {
            int sid = tid + 256 * i;
            int arr = sid >> 9, rc = sid & 511, row = rc >> 3, c8 = rc & 7;
            const __nv_bfloat16* s = (arr == 0 ? g_kh : arr == 1 ? g_kl :
                                      arr == 2 ? g_vh : g_vl);
            const __nv_bfloat16* src = s + (tb + kt * 64 + row) * Dm + h * 64 + c8 * 8;
            CP_ASYNC16(sb + st * 32768 + arr * 8192 + (uint32_t)(((row >> 3) * 8 + c8) * 128
                       + (((row & 7) ^ c8) << 4)), src);
        }
    };

    fillkv(0, 0); CP_COMMIT();

    for (int kt = 0; kt < nkv; kt++) {
        if (kt + 1 < nkv) { fillkv((kt + 1) & 1, kt + 1); CP_COMMIT(); CP_WAIT1(); }
        else              { CP_WAIT0(); }
        __syncthreads();

        const uint32_t kbb = sb + (kt & 1) * 32768;
        float s[8][4];
        #pragma unroll
        for (int nj = 0; nj < 8; nj++)
            #pragma unroll
            for (int c = 0; c < 4; c++) s[nj][c] = 0.f;

        // S = Qh*Kh + Qh*Kl + Ql*Kh
        #pragma unroll
        for (int ks = 0; ks < 4; ks++) {
            #pragma unroll
            for (int njp = 0; njp < 4; njp++) {
                int krow = njp * 16 + (lane >> 4) * 8 + (lane & 7);
                uint32_t off = swo(krow, ks * 16 + ((lane >> 3) & 1) * 8);
                uint32_t kbh[4], kbl[4];
                ldmat4(kbh, kbb + off);
                ldmat4(kbl, kbb + 8192 + off);
                mma16816(s[2 * njp],     qh[ks], kbh[0], kbh[1]);
                mma16816(s[2 * njp + 1], qh[ks], kbh[2], kbh[3]);
                mma16816(s[2 * njp],     qh[ks], kbl[0], kbl[1]);
                mma16816(s[2 * njp + 1], qh[ks], kbl[2], kbl[3]);
                mma16816(s[2 * njp],     ql[ks], kbh[0], kbh[1]);
                mma16816(s[2 * njp + 1], ql[ks], kbh[2], kbh[3]);
            }
        }

        // causal mask
        const int rowA = q0 + 16 * w + (lane >> 2);
        if (kt * 64 + 63 > q0 + 16 * w) {
            #pragma unroll
            for (int nj = 0; nj < 8; nj++)
                #pragma unroll
                for (int c = 0; c < 4; c++) {
                    int col = kt * 64 + nj * 8 + (lane & 3) * 2 + (c & 1);
                    if (col > rowA + (c >> 1) * 8) s[nj][c] = -1e30f;
                }
        }

        // online softmax (fma-pipe exp)
        float mxA = -1e30f, mxB = -1e30f;
        #pragma unroll
        for (int nj = 0; nj < 8; nj++) {
            mxA = fmaxf(mxA, fmaxf(s[nj][0], s[nj][1]));
            mxB = fmaxf(mxB, fmaxf(s[nj][2], s[nj][3]));
        }
        #pragma unroll
        for (int off = 1; off < 4; off <<= 1) {
            mxA = fmaxf(mxA, __shfl_xor_sync(0xffffffffu, mxA, off));
            mxB = fmaxf(mxB, __shfl_xor_sync(0xffffffffu, mxB, off));
        }
        float mA = fmaxf(m[0], mxA), mB = fmaxf(m[1], mxB);
        float scA = fexp(m[0] - mA), scB = fexp(m[1] - mB);
        m[0] = mA; m[1] = mB;
        float sA = 0.f, sB = 0.f;
        #pragma unroll
        for (int nj = 0; nj < 8; nj++) {
            s[nj][0] = fexp(s[nj][0] - mA); s[nj][1] = fexp(s[nj][1] - mA);
            s[nj][2] = fexp(s[nj][2] - mB); s[nj][3] = fexp(s[nj][3] - mB);
            sA += s[nj][0] + s[nj][1];
            sB += s[nj][2] + s[nj][3];
        }
        #pragma unroll
        for (int off = 1; off < 4; off <<= 1) {
            sA += __shfl_xor_sync(0xffffffffu, sA, off);
            sB += __shfl_xor_sync(0xffffffffu, sB, off);
        }
        l[0] = l[0] * scA + sA;
        l[1] = l[1] * scB + sB;
        #pragma unroll
        for (int nj = 0; nj < 8; nj++) {
            o[nj][0] *= scA; o[nj][1] *= scA; o[nj][2] *= scB; o[nj][3] *= scB;
        }

        // O += Ph*Vh + Ph*Vl + Pl*Vh
        const uint32_t vbb = kbb + 16384;
        #pragma unroll
        for (int kk = 0; kk < 4; kk++) {
            uint32_t pah[4], pal[4];
            pack_pair(pah[0], pal[0], s[2 * kk][0],     s[2 * kk][1]);
            pack_pair(pah[1], pal[1], s[2 * kk][2],     s[2 * kk][3]);
            pack_pair(pah[2], pal[2], s[2 * kk + 1][0], s[2 * kk + 1][1]);
            pack_pair(pah[3], pal[3], s[2 * kk + 1][2], s[2 * kk + 1][3]);
            int vrow = kk * 16 + (lane & 7) + ((lane >> 3) & 1) * 8;
            #pragma unroll
            for (int ep = 0; ep < 4; ep++) {
                uint32_t off = swo(vrow, ep * 16 + (lane >> 4) * 8);
                uint32_t vbh[4], vbl[4];
                ldmat4t(vbh, vbb + off);
                ldmat4t(vbl, vbb + 8192 + off);
                mma16816(o[2 * ep],     pah, vbh[0], vbh[1]);
                mma16816(o[2 * ep + 1], pah, vbh[2], vbh[3]);
                mma16816(o[2 * ep],     pah, vbl[0], vbl[1]);
                mma16816(o[2 * ep + 1], pah, vbl[2], vbl[3]);
                mma16816(o[2 * ep],     pal, vbh[0], vbh[1]);
                mma16816(o[2 * ep + 1], pal, vbh[2], vbh[3]);
            }
        }
        __syncthreads();
    }

    // write z split
    const float invA = 1.f / l[0], invB = 1.f / l[1];
    const size_t base = (tq0 + 16 * w + (lane >> 2)) * Dm + h * 64;
    #pragma unroll
    for (int nj = 0; nj < 8; nj++) {
        const int col = nj * 8 + (lane & 3) * 2;
        split_store(g_zh, g_zl, base + col,          o[nj][0] * invA, o[nj][1] * invA);
        split_store(g_zh, g_zl, base + 8 * Dm + col, o[nj][2] * invB, o[nj][3] * invB);
    }
}

// ---------------------------------------------------------------------------
extern "C" void kernel_launch(void* const* d_in, const int* in_sizes, int n_in,
                              void* d_out, int out_size)
{
    const float* x  = (const float*)d_in[0];
    const float* wq = (const float*)d_in[1];
    const float* bq = (const float*)d_in[2];
    const float* wk = (const float*)d_in[3];
    const float* bk = (const float*)d_in[4];
    const float* wv = (const float*)d_in[5];
    const float* bv = (const float*)d_in[6];
    const float* wo = (const float*)d_in[7];
    const float* bo = (const float*)d_in[8];
    float* out = (float*)d_out;

    cudaFuncSetAttribute(hmma_gemm, cudaFuncAttributeMaxDynamicSharedMemorySize, GEMM_SMEM);
    cudaFuncSetAttribute(fattn,     cudaFuncAttributeMaxDynamicSharedMemorySize, ATT_SMEM);

    void* p;
    cudaGetSymbolAddress(&p, g_xh); __nv_bfloat16* xh = (__nv_bfloat16*)p;
    cudaGetSymbolAddress(&p, g_xl); __nv_bfloat16* xl = (__nv_bfloat16*)p;
    cudaGetSymbolAddress(&p, g_zh); __nv_bfloat16* zh = (__nv_bfloat16*)p;
    cudaGetSymbolAddress(&p, g_zl); __nv_bfloat16* zl = (__nv_bfloat16*)p;
    cudaGetSymbolAddress(&p, g_wh); __nv_bfloat16* wh = (__nv_bfloat16*)p;
    cudaGetSymbolAddress(&p, g_wl); __nv_bfloat16* wl = (__nv_bfloat16*)p;
    cudaGetSymbolAddress(&p, g_oh); __nv_bfloat16* oh = (__nv_bfloat16*)p;
    cudaGetSymbolAddress(&p, g_ol); __nv_bfloat16* ol = (__nv_bfloat16*)p;

    conv_split<<<(Tt * Dm / 4 + 255) / 256, 256>>>(x, xh, xl, Tt * Dm / 4);
    conv_wqkv<<<(3 * Dm * Dm + 255) / 256, 256>>>(wq, wk, wv);
    conv_wo<<<(Dm * Dm + 255) / 256, 256>>>(wo);

    // QKV projection -> split bf16 Q(*0.125)/K/V
    hmma_gemm<<<dim3(Tt / 128, 24), 256, GEMM_SMEM>>>(
        xh, xl, wh, wl, bq, bk, bv, nullptr, 1);

    // flash attention -> split bf16 z
    fattn<<<dim3(Sq / 128, Hh, Bsz), 256, ATT_SMEM>>>();

    // output projection -> fp32 out
    hmma_gemm<<<dim3(Tt / 128, 8), 256, GEMM_SMEM>>>(
        zh, zl, oh, ol, bo, bo, bo, out, 0);
}

// round 6
// speedup vs baseline: 1.7092x; 1.1104x over previous
#include <cuda_runtime.h>
#include <cuda_bf16.h>
#include <cstdint>

#define Bsz 4
#define Sq  2048
#define Dm  1024
#define Hh  16
#define Dh  64
#define Tt  (Bsz * Sq)

// ---------------- scratch ----------------
__device__ __nv_bfloat16 g_xh[(size_t)Tt * Dm];
__device__ __nv_bfloat16 g_xl[(size_t)Tt * Dm];
__device__ __nv_bfloat16 g_wh[(size_t)3 * Dm * Dm];
__device__ __nv_bfloat16 g_wl[(size_t)3 * Dm * Dm];
__device__ __nv_bfloat16 g_oh[(size_t)Dm * Dm];
__device__ __nv_bfloat16 g_ol[(size_t)Dm * Dm];
__device__ __nv_bfloat16 g_qh[(size_t)Tt * Dm];
__device__ __nv_bfloat16 g_ql[(size_t)Tt * Dm];
__device__ __nv_bfloat16 g_kh[(size_t)Tt * Dm];
__device__ __nv_bfloat16 g_kl[(size_t)Tt * Dm];
__device__ __nv_bfloat16 g_vh[(size_t)Tt * Dm];
__device__ __nv_bfloat16 g_vl[(size_t)Tt * Dm];
__device__ __nv_bfloat16 g_zh[(size_t)Tt * Dm];
__device__ __nv_bfloat16 g_zl[(size_t)Tt * Dm];

// ---------------- helpers (arch-stable PTX only) ----------------
__device__ __forceinline__ uint32_t smem_u32(const void* p) {
    uint32_t a;
    asm("{ .reg .u64 t; cvta.to.shared.u64 t, %1; cvt.u32.u64 %0, t; }" : "=r"(a) : "l"(p));
    return a;
}
#define CP_ASYNC16(dst, src) \
    asm volatile("cp.async.cg.shared.global [%0], [%1], 16;" :: "r"(dst), "l"(src))
#define CP_COMMIT() asm volatile("cp.async.commit_group;" ::: "memory")
#define CP_WAIT1()  asm volatile("cp.async.wait_group 1;" ::: "memory")
#define CP_WAIT0()  asm volatile("cp.async.wait_group 0;" ::: "memory")

__device__ __forceinline__ void ldmat4(uint32_t r[4], uint32_t a) {
    asm volatile("ldmatrix.sync.aligned.m8n8.x4.shared.b16 {%0,%1,%2,%3}, [%4];"
                 : "=r"(r[0]), "=r"(r[1]), "=r"(r[2]), "=r"(r[3]) : "r"(a));
}
__device__ __forceinline__ void ldmat4t(uint32_t r[4], uint32_t a) {
    asm volatile("ldmatrix.sync.aligned.m8n8.x4.trans.shared.b16 {%0,%1,%2,%3}, [%4];"
                 : "=r"(r[0]), "=r"(r[1]), "=r"(r[2]), "=r"(r[3]) : "r"(a));
}
__device__ __forceinline__ void mma16816(float* c, const uint32_t* a,
                                         uint32_t b0, uint32_t b1) {
    asm volatile("mma.sync.aligned.m16n8k16.row.col.f32.bf16.bf16.f32 "
                 "{%0,%1,%2,%3}, {%4,%5,%6,%7}, {%8,%9}, {%0,%1,%2,%3};"
                 : "+f"(c[0]), "+f"(c[1]), "+f"(c[2]), "+f"(c[3])
                 : "r"(a[0]), "r"(a[1]), "r"(a[2]), "r"(a[3]), "r"(b0), "r"(b1));
}
#define CVT2(res, hi, lo) \
    asm("cvt.rn.bf16x2.f32 %0, %1, %2;" : "=r"(res) : "f"(hi), "f"(lo))

// fast exp on fma/alu pipes (x <= 0, clamped; ~1e-7 rel err)
__device__ __forceinline__ float fexp(float x) {
    x = fmaxf(x, -80.f);
    float t = x * 1.44269504f;
    float fk = t + 12582912.f;
    int   i  = __float_as_int(fk) - 0x4B400000;
    float f  = t - (fk - 12582912.f);
    float p = 1.33978e-3f;
    p = fmaf(p, f, 9.67839e-3f);
    p = fmaf(p, f, 5.55041e-2f);
    p = fmaf(p, f, 2.40227e-1f);
    p = fmaf(p, f, 6.93147e-1f);
    p = fmaf(p, f, 1.0f);
    return __int_as_float(__float_as_int(p) + (i << 23));
}
__device__ __forceinline__ void pack_pair(uint32_t& hv, uint32_t& lv, float v0, float v1) {
    CVT2(hv, v1, v0);
    float f0 = __uint_as_float(hv << 16);
    float f1 = __uint_as_float(hv & 0xFFFF0000u);
    CVT2(lv, v1 - f1, v0 - f0);
}
__device__ __forceinline__ void split_store(__nv_bfloat16* H, __nv_bfloat16* L,
                                            size_t idx, float v0, float v1) {
    uint32_t hv, lv;
    pack_pair(hv, lv, v0, v1);
    *(uint32_t*)(H + idx) = hv;
    *(uint32_t*)(L + idx) = lv;
}

// ---------------- prep ----------------
__global__ void conv_split(const float* __restrict__ in, __nv_bfloat16* __restrict__ hi,
                           __nv_bfloat16* __restrict__ lo, int n4)
{
    int i = blockIdx.x * blockDim.x + threadIdx.x;
    if (i >= n4) return;
    float4 v = ((const float4*)in)[i];
    uint32_t h0, h1, l0, l1;
    pack_pair(h0, l0, v.x, v.y);
    pack_pair(h1, l1, v.z, v.w);
    ((uint32_t*)hi)[2 * i] = h0; ((uint32_t*)hi)[2 * i + 1] = h1;
    ((uint32_t*)lo)[2 * i] = l0; ((uint32_t*)lo)[2 * i + 1] = l1;
}
__global__ void conv_wqkv(const float* __restrict__ wq, const float* __restrict__ wk,
                          const float* __restrict__ wv)
{
    int id = blockIdx.x * 256 + threadIdx.x;
    if (id >= 3 * Dm * Dm) return;
    int n = id >> 10, d = id & 1023;
    int proj = n >> 10, nl = n & 1023, h = nl >> 6, e = nl & 63;
    const float* W = (proj == 0 ? wq : proj == 1 ? wk : wv);
    float v = W[((size_t)h * Dm + d) * Dh + e];
    __nv_bfloat16 hh = __float2bfloat16(v);
    g_wh[id] = hh;
    g_wl[id] = __float2bfloat16(v - __bfloat162float(hh));
}
__global__ void conv_wo(const float* __restrict__ wo)
{
    int id = blockIdx.x * 256 + threadIdx.x;
    if (id >= Dm * Dm) return;
    int n = id >> 10, k = id & 1023;
    float v = wo[(size_t)k * Dm + n];
    __nv_bfloat16 hh = __float2bfloat16(v);
    g_oh[id] = hh;
    g_ol[id] = __float2bfloat16(v - __bfloat162float(hh));
}

// ---------------- bf16x3 HMMA GEMM (2 CTAs/SM, ks-outer mainloop) -----------
#define ARR_BYTES 8192
#define BUF_BYTES (4 * ARR_BYTES)
#define GEMM_SMEM (2 * BUF_BYTES)

__global__ __launch_bounds__(256, 2) void hmma_gemm(
    const __nv_bfloat16* __restrict__ Ah, const __nv_bfloat16* __restrict__ Al,
    const __nv_bfloat16* __restrict__ Bh, const __nv_bfloat16* __restrict__ Bl,
    const float* __restrict__ b0, const float* __restrict__ b1,
    const float* __restrict__ b2, float* __restrict__ C, int mode)
{
    extern __shared__ char smc[];
    const uint32_t sb = smem_u32(smc);
    const int tid = threadIdx.x, wid = tid >> 5, lane = tid & 31;
    const int warp_m = wid >> 2, warp_n = wid & 3;
    const int g = lane >> 3, r = lane & 7;
    const int m0  = blockIdx.x * 128;
    const int n0g = blockIdx.y * 128;
    const int proj = n0g >> 10;
    const int nl   = n0g & 1023;
    const float* bias = (proj == 0 ? b0 : proj == 1 ? b1 : b2);

    const __nv_bfloat16* srcs[4];
    srcs[0] = Ah + (size_t)m0  * Dm;
    srcs[1] = Al + (size_t)m0  * Dm;
    srcs[2] = Bh + (size_t)n0g * Dm;
    srcs[3] = Bl + (size_t)n0g * Dm;

    const uint32_t aoff0 = (uint32_t)(((warp_m * 8 + (g & 1)) * 4 + (g >> 1)) * 128 + r * 16);
    const uint32_t boff0 = (uint32_t)(((warp_n * 4 + (g >> 1)) * 4 + (g & 1)) * 128 + r * 16);

    auto fill = [&](int buf, int k0) {
        #pragma unroll
        for (int arr = 0; arr < 4; arr++) {
            uint32_t abase = sb + buf * BUF_BYTES + arr * ARR_BYTES;
            const __nv_bfloat16* s = srcs[arr];
            #pragma unroll
            for (int i = 0; i < 2; i++) {
                int cid = tid + 256 * i;
                int row = cid >> 2, kc = (cid & 3) * 8;
                const void* gsrc = s + (size_t)row * Dm + k0 + kc;
                uint32_t soff = abase + (uint32_t)(((row >> 3) * 4 + (kc >> 3)) * 128
                                                   + (row & 7) * 16);
                CP_ASYNC16(soff, gsrc);
            }
        }
    };

    float acc[4][4][4];
    #pragma unroll
    for (int mi = 0; mi < 4; mi++)
        #pragma unroll
        for (int nj = 0; nj < 4; nj++)
            #pragma unroll
            for (int c = 0; c < 4; c++) acc[mi][nj][c] = 0.f;

    fill(0, 0);
    CP_COMMIT();

    const int NIT = Dm / 32;
    for (int it = 0; it < NIT; it++) {
        if (it + 1 < NIT) { fill((it + 1) & 1, (it + 1) * 32); CP_COMMIT(); CP_WAIT1(); }
        else              { CP_WAIT0(); }
        __syncthreads();

        const uint32_t bufb = sb + (it & 1) * BUF_BYTES;
        const uint32_t bAh = bufb, bAl = bufb + ARR_BYTES;
        const uint32_t bBh = bufb + 2 * ARR_BYTES, bBl = bufb + 3 * ARR_BYTES;

        // ks-outer: only one k-step of A-frags live at a time (reg pressure)
        #pragma unroll
        for (int ks = 0; ks < 2; ks++) {
            uint32_t afr[4][4];
            uint32_t bh[2][4], bl[2][4];
            ldmat4(bh[0], bBh + boff0 + ks * 256);
            ldmat4(bh[1], bBh + boff0 + 1024 + ks * 256);
            ldmat4(bl[0], bBl + boff0 + ks * 256);
            ldmat4(bl[1], bBl + boff0 + 1024 + ks * 256);
            #pragma unroll
            for (int mi = 0; mi < 4; mi++)
                ldmat4(afr[mi], bAh + aoff0 + mi * 1024 + ks * 256);
            #pragma unroll
            for (int mi = 0; mi < 4; mi++)
                #pragma unroll
                for (int nj = 0; nj < 4; nj++) {
                    mma16816(acc[mi][nj], afr[mi],
                             bh[nj >> 1][(nj & 1) * 2], bh[nj >> 1][(nj & 1) * 2 + 1]);
                    mma16816(acc[mi][nj], afr[mi],
                             bl[nj >> 1][(nj & 1) * 2], bl[nj >> 1][(nj & 1) * 2 + 1]);
                }
            #pragma unroll
            for (int mi = 0; mi < 4; mi++)
                ldmat4(afr[mi], bAl + aoff0 + mi * 1024 + ks * 256);
            #pragma unroll
            for (int mi = 0; mi < 4; mi++)
                #pragma unroll
                for (int nj = 0; nj < 4; nj++)
                    mma16816(acc[mi][nj], afr[mi],
                             bh[nj >> 1][(nj & 1) * 2], bh[nj >> 1][(nj & 1) * 2 + 1]);
        }
        __syncthreads();
    }

    // epilogue
    const int gq = lane >> 2, tq = lane & 3;
    if (mode == 0) {
        #pragma unroll
        for (int mi = 0; mi < 4; mi++) {
            const int row = m0 + warp_m * 64 + mi * 16 + gq;
            #pragma unroll
            for (int nj = 0; nj < 4; nj++) {
                const int col = nl + warp_n * 32 + nj * 8 + tq * 2;
                const float bv0 = bias[col], bv1 = bias[col + 1];
                *(float2*)(C + (size_t)row * Dm + col) =
                    make_float2(acc[mi][nj][0] + bv0, acc[mi][nj][1] + bv1);
                *(float2*)(C + (size_t)(row + 8) * Dm + col) =
                    make_float2(acc[mi][nj][2] + bv0, acc[mi][nj][3] + bv1);
            }
        }
    } else {
        __nv_bfloat16* H = (proj == 0 ? g_qh : proj == 1 ? g_kh : g_vh);
        __nv_bfloat16* L = (proj == 0 ? g_ql : proj == 1 ? g_kl : g_vl);
        const float sc = (proj == 0) ? 0.125f : 1.f;
        #pragma unroll
        for (int mi = 0; mi < 4; mi++) {
            const size_t row = (size_t)(m0 + warp_m * 64 + mi * 16 + gq);
            #pragma unroll
            for (int nj = 0; nj < 4; nj++) {
                const int col = nl + warp_n * 32 + nj * 8 + tq * 2;
                const float bv0 = bias[col], bv1 = bias[col + 1];
                split_store(H, L, row * Dm + col,
                            (acc[mi][nj][0] + bv0) * sc, (acc[mi][nj][1] + bv1) * sc);
                split_store(H, L, (row + 8) * Dm + col,
                            (acc[mi][nj][2] + bv0) * sc, (acc[mi][nj][3] + bv1) * sc);
            }
        }
    }
}

// ---------------- HMMA flash attention (unchanged from R5) ----------------
#define ATT_SMEM 65536
__device__ __forceinline__ uint32_t swo(int row, int e) {
    return (uint32_t)(((row >> 3) * 8 + (e >> 3)) * 128 + (((row & 7) ^ (e >> 3)) << 4));
}

__global__ __launch_bounds__(256) void fattn()
{
    extern __shared__ char sm[];
    const uint32_t sb = smem_u32(sm);
    const int tid = threadIdx.x, w = tid >> 5, lane = tid & 31;
    const int qb = blockIdx.x, h = blockIdx.y, b = blockIdx.z;
    const int q0 = qb * 128;
    const size_t tq0 = (size_t)b * Sq + q0;

    #pragma unroll
    for (int i = 0; i < 8; i++) {
        int sid = tid + 256 * i;
        int arr = sid >> 10, rc = sid & 1023, row = rc >> 3, c8 = rc & 7;
        const __nv_bfloat16* src = (arr ? g_ql : g_qh) + (tq0 + row) * Dm + h * 64 + c8 * 8;
        CP_ASYNC16(sb + arr * 16384 + (uint32_t)(((row >> 3) * 8 + c8) * 128
                   + (((row & 7) ^ c8) << 4)), src);
    }
    CP_COMMIT(); CP_WAIT0(); __syncthreads();

    uint32_t qh[4][4], ql[4][4];
    {
        int row = 16 * w + (lane & 7) + ((lane >> 3) & 1) * 8;
        #pragma unroll
        for (int ks = 0; ks < 4; ks++) {
            uint32_t off = swo(row, ks * 16 + (lane >> 4) * 8);
            ldmat4(qh[ks], sb + off);
            ldmat4(ql[ks], sb + 16384 + off);
        }
    }
    __syncthreads();

    float o[8][4], m[2] = {-1e30f, -1e30f}, l[2] = {0.f, 0.f};
    #pragma unroll
    for (int nj = 0; nj < 8; nj++)
        #pragma unroll
        for (int c = 0; c < 4; c++) o[nj][c] = 0.f;

    const int nkv = 2 * qb + 2;
    const size_t tb = (size_t)b * Sq;

    auto fillkv = [&](int st, int kt) {
        #pragma unroll
        for (int i = 0; i < 8; i++) {
            int sid = tid + 256 * i;
            int arr = sid >> 9, rc = sid & 511, row = rc >> 3, c8 = rc & 7;
            const __nv_bfloat16* s = (arr == 0 ? g_kh : arr == 1 ? g_kl :
                                      arr == 2 ? g_vh : g_vl);
            const __nv_bfloat16* src = s + (tb + kt * 64 + row) * Dm + h * 64 + c8 * 8;
            CP_ASYNC16(sb + st * 32768 + arr * 8192 + (uint32_t)(((row >> 3) * 8 + c8) * 128
                       + (((row & 7) ^ c8) << 4)), src);
        }
    };

    fillkv(0, 0); CP_COMMIT();

    for (int kt = 0; kt < nkv; kt++) {
        if (kt + 1 < nkv) { fillkv((kt + 1) & 1, kt + 1); CP_COMMIT(); CP_WAIT1(); }
        else              { CP_WAIT0(); }
        __syncthreads();

        const uint32_t kbb = sb + (kt & 1) * 32768;
        float s[8][4];
        #pragma unroll
        for (int nj = 0; nj < 8; nj++)
            #pragma unroll
            for (int c = 0; c < 4; c++) s[nj][c] = 0.f;

        #pragma unroll
        for (int ks = 0; ks < 4; ks++) {
            #pragma unroll
            for (int njp = 0; njp < 4; njp++) {
                int krow = njp * 16 + (lane >> 4) * 8 + (lane & 7);
                uint32_t off = swo(krow, ks * 16 + ((lane >> 3) & 1) * 8);
                uint32_t kbh[4], kbl[4];
                ldmat4(kbh, kbb + off);
                ldmat4(kbl, kbb + 8192 + off);
                mma16816(s[2 * njp],     qh[ks], kbh[0], kbh[1]);
                mma16816(s[2 * njp + 1], qh[ks], kbh[2], kbh[3]);
                mma16816(s[2 * njp],     qh[ks], kbl[0], kbl[1]);
                mma16816(s[2 * njp + 1], qh[ks], kbl[2], kbl[3]);
                mma16816(s[2 * njp],     ql[ks], kbh[0], kbh[1]);
                mma16816(s[2 * njp + 1], ql[ks], kbh[2], kbh[3]);
            }
        }

        const int rowA = q0 + 16 * w + (lane >> 2);
        if (kt * 64 + 63 > q0 + 16 * w) {
            #pragma unroll
            for (int nj = 0; nj < 8; nj++)
                #pragma unroll
                for (int c = 0; c < 4; c++) {
                    int col = kt * 64 + nj * 8 + (lane & 3) * 2 + (c & 1);
                    if (col > rowA + (c >> 1) * 8) s[nj][c] = -1e30f;
                }
        }

        float mxA = -1e30f, mxB = -1e30f;
        #pragma unroll
        for (int nj = 0; nj < 8; nj++) {
            mxA = fmaxf(mxA, fmaxf(s[nj][0], s[nj][1]));
            mxB = fmaxf(mxB, fmaxf(s[nj][2], s[nj][3]));
        }
        #pragma unroll
        for (int off = 1; off < 4; off <<= 1) {
            mxA = fmaxf(mxA, __shfl_xor_sync(0xffffffffu, mxA, off));
            mxB = fmaxf(mxB, __shfl_xor_sync(0xffffffffu, mxB, off));
        }
        float mA = fmaxf(m[0], mxA), mB = fmaxf(m[1], mxB);
        float scA = fexp(m[0] - mA), scB = fexp(m[1] - mB);
        m[0] = mA; m[1] = mB;
        float sA = 0.f, sB = 0.f;
        #pragma unroll
        for (int nj = 0; nj < 8; nj++) {
            s[nj][0] = fexp(s[nj][0] - mA); s[nj][1] = fexp(s[nj][1] - mA);
            s[nj][2] = fexp(s[nj][2] - mB); s[nj][3] = fexp(s[nj][3] - mB);
            sA += s[nj][0] + s[nj][1];
            sB += s[nj][2] + s[nj][3];
        }
        #pragma unroll
        for (int off = 1; off < 4; off <<= 1) {
            sA += __shfl_xor_sync(0xffffffffu, sA, off);
            sB += __shfl_xor_sync(0xffffffffu, sB, off);
        }
        l[0] = l[0] * scA + sA;
        l[1] = l[1] * scB + sB;
        #pragma unroll
        for (int nj = 0; nj < 8; nj++) {
            o[nj][0] *= scA; o[nj][1] *= scA; o[nj][2] *= scB; o[nj][3] *= scB;
        }

        const uint32_t vbb = kbb + 16384;
        #pragma unroll
        for (int kk = 0; kk < 4; kk++) {
            uint32_t pah[4], pal[4];
            pack_pair(pah[0], pal[0], s[2 * kk][0],     s[2 * kk][1]);
            pack_pair(pah[1], pal[1], s[2 * kk][2],     s[2 * kk][3]);
            pack_pair(pah[2], pal[2], s[2 * kk + 1][0], s[2 * kk + 1][1]);
            pack_pair(pah[3], pal[3], s[2 * kk + 1][2], s[2 * kk + 1][3]);
            int vrow = kk * 16 + (lane & 7) + ((lane >> 3) & 1) * 8;
            #pragma unroll
            for (int ep = 0; ep < 4; ep++) {
                uint32_t off = swo(vrow, ep * 16 + (lane >> 4) * 8);
                uint32_t vbh[4], vbl[4];
                ldmat4t(vbh, vbb + off);
                ldmat4t(vbl, vbb + 8192 + off);
                mma16816(o[2 * ep],     pah, vbh[0], vbh[1]);
                mma16816(o[2 * ep + 1], pah, vbh[2], vbh[3]);
                mma16816(o[2 * ep],     pah, vbl[0], vbl[1]);
                mma16816(o[2 * ep + 1], pah, vbl[2], vbl[3]);
                mma16816(o[2 * ep],     pal, vbh[0], vbh[1]);
                mma16816(o[2 * ep + 1], pal, vbh[2], vbh[3]);
            }
        }
        __syncthreads();
    }

    const float invA = 1.f / l[0], invB = 1.f / l[1];
    const size_t base = (tq0 + 16 * w + (lane >> 2)) * Dm + h * 64;
    #pragma unroll
    for (int nj = 0; nj < 8; nj++) {
        const int col = nj * 8 + (lane & 3) * 2;
        split_store(g_zh, g_zl, base + col,          o[nj][0] * invA, o[nj][1] * invA);
        split_store(g_zh, g_zl, base + 8 * Dm + col, o[nj][2] * invB, o[nj][3] * invB);
    }
}

// ---------------------------------------------------------------------------
extern "C" void kernel_launch(void* const* d_in, const int* in_sizes, int n_in,
                              void* d_out, int out_size)
{
    const float* x  = (const float*)d_in[0];
    const float* wq = (const float*)d_in[1];
    const float* bq = (const float*)d_in[2];
    const float* wk = (const float*)d_in[3];
    const float* bk = (const float*)d_in[4];
    const float* wv = (const float*)d_in[5];
    const float* bv = (const float*)d_in[6];
    const float* wo = (const float*)d_in[7];
    const float* bo = (const float*)d_in[8];
    float* out = (float*)d_out;

    cudaFuncSetAttribute(hmma_gemm, cudaFuncAttributeMaxDynamicSharedMemorySize, GEMM_SMEM);
    cudaFuncSetAttribute(fattn,     cudaFuncAttributeMaxDynamicSharedMemorySize, ATT_SMEM);

    void* p;
    cudaGetSymbolAddress(&p, g_xh); __nv_bfloat16* xh = (__nv_bfloat16*)p;
    cudaGetSymbolAddress(&p, g_xl); __nv_bfloat16* xl = (__nv_bfloat16*)p;
    cudaGetSymbolAddress(&p, g_zh); __nv_bfloat16* zh = (__nv_bfloat16*)p;
    cudaGetSymbolAddress(&p, g_zl); __nv_bfloat16* zl = (__nv_bfloat16*)p;
    cudaGetSymbolAddress(&p, g_wh); __nv_bfloat16* wh = (__nv_bfloat16*)p;
    cudaGetSymbolAddress(&p, g_wl); __nv_bfloat16* wl = (__nv_bfloat16*)p;
    cudaGetSymbolAddress(&p, g_oh); __nv_bfloat16* oh = (__nv_bfloat16*)p;
    cudaGetSymbolAddress(&p, g_ol); __nv_bfloat16* ol = (__nv_bfloat16*)p;

    conv_split<<<(Tt * Dm / 4 + 255) / 256, 256>>>(x, xh, xl, Tt * Dm / 4);
    conv_wqkv<<<(3 * Dm * Dm + 255) / 256, 256>>>(wq, wk, wv);
    conv_wo<<<(Dm * Dm + 255) / 256, 256>>>(wo);

    hmma_gemm<<<dim3(Tt / 128, 24), 256, GEMM_SMEM>>>(
        xh, xl, wh, wl, bq, bk, bv, nullptr, 1);

    fattn<<<dim3(Sq / 128, Hh, Bsz), 256, ATT_SMEM>>>();

    hmma_gemm<<<dim3(Tt / 128, 8), 256, GEMM_SMEM>>>(
        zh, zl, oh, ol, bo, bo, bo, out, 0);
}

// round 7
// speedup vs baseline: 1.7530x; 1.0256x over previous
#include <cuda_runtime.h>
#include <cuda_bf16.h>
#include <cstdint>

#define Bsz 4
#define Sq  2048
#define Dm  1024
#define Hh  16
#define Dh  64
#define Tt  (Bsz * Sq)

// ---------------- scratch ----------------
__device__ __nv_bfloat16 g_xh[(size_t)Tt * Dm];
__device__ __nv_bfloat16 g_xl[(size_t)Tt * Dm];
__device__ __nv_bfloat16 g_wh[(size_t)3 * Dm * Dm];
__device__ __nv_bfloat16 g_wl[(size_t)3 * Dm * Dm];
__device__ __nv_bfloat16 g_oh[(size_t)Dm * Dm];
__device__ __nv_bfloat16 g_ol[(size_t)Dm * Dm];
__device__ __nv_bfloat16 g_qh[(size_t)Tt * Dm];
__device__ __nv_bfloat16 g_ql[(size_t)Tt * Dm];
__device__ __nv_bfloat16 g_kh[(size_t)Tt * Dm];
__device__ __nv_bfloat16 g_kl[(size_t)Tt * Dm];
__device__ __nv_bfloat16 g_vh[(size_t)Tt * Dm];
__device__ __nv_bfloat16 g_vl[(size_t)Tt * Dm];
__device__ __nv_bfloat16 g_zh[(size_t)Tt * Dm];
__device__ __nv_bfloat16 g_zl[(size_t)Tt * Dm];

// ---------------- helpers (arch-stable PTX only) ----------------
__device__ __forceinline__ uint32_t smem_u32(const void* p) {
    uint32_t a;
    asm("{ .reg .u64 t; cvta.to.shared.u64 t, %1; cvt.u32.u64 %0, t; }" : "=r"(a) : "l"(p));
    return a;
}
#define CP_ASYNC16(dst, src) \
    asm volatile("cp.async.cg.shared.global [%0], [%1], 16;" :: "r"(dst), "l"(src))
#define CP_COMMIT() asm volatile("cp.async.commit_group;" ::: "memory")
#define CP_WAIT1()  asm volatile("cp.async.wait_group 1;" ::: "memory")
#define CP_WAIT0()  asm volatile("cp.async.wait_group 0;" ::: "memory")

__device__ __forceinline__ void ldmat4(uint32_t r[4], uint32_t a) {
    asm volatile("ldmatrix.sync.aligned.m8n8.x4.shared.b16 {%0,%1,%2,%3}, [%4];"
                 : "=r"(r[0]), "=r"(r[1]), "=r"(r[2]), "=r"(r[3]) : "r"(a));
}
__device__ __forceinline__ void ldmat4t(uint32_t r[4], uint32_t a) {
    asm volatile("ldmatrix.sync.aligned.m8n8.x4.trans.shared.b16 {%0,%1,%2,%3}, [%4];"
                 : "=r"(r[0]), "=r"(r[1]), "=r"(r[2]), "=r"(r[3]) : "r"(a));
}
__device__ __forceinline__ void mma16816(float* c, const uint32_t* a,
                                         uint32_t b0, uint32_t b1) {
    asm volatile("mma.sync.aligned.m16n8k16.row.col.f32.bf16.bf16.f32 "
                 "{%0,%1,%2,%3}, {%4,%5,%6,%7}, {%8,%9}, {%0,%1,%2,%3};"
                 : "+f"(c[0]), "+f"(c[1]), "+f"(c[2]), "+f"(c[3])
                 : "r"(a[0]), "r"(a[1]), "r"(a[2]), "r"(a[3]), "r"(b0), "r"(b1));
}
#define CVT2(res, hi, lo) \
    asm("cvt.rn.bf16x2.f32 %0, %1, %2;" : "=r"(res) : "f"(hi), "f"(lo))

__device__ __forceinline__ float fexp(float x) {
    x = fmaxf(x, -80.f);
    float t = x * 1.44269504f;
    float fk = t + 12582912.f;
    int   i  = __float_as_int(fk) - 0x4B400000;
    float f  = t - (fk - 12582912.f);
    float p = 1.33978e-3f;
    p = fmaf(p, f, 9.67839e-3f);
    p = fmaf(p, f, 5.55041e-2f);
    p = fmaf(p, f, 2.40227e-1f);
    p = fmaf(p, f, 6.93147e-1f);
    p = fmaf(p, f, 1.0f);
    return __int_as_float(__float_as_int(p) + (i << 23));
}
__device__ __forceinline__ void pack_pair(uint32_t& hv, uint32_t& lv, float v0, float v1) {
    CVT2(hv, v1, v0);
    float f0 = __uint_as_float(hv << 16);
    float f1 = __uint_as_float(hv & 0xFFFF0000u);
    CVT2(lv, v1 - f1, v0 - f0);
}
__device__ __forceinline__ void split_store(__nv_bfloat16* H, __nv_bfloat16* L,
                                            size_t idx, float v0, float v1) {
    uint32_t hv, lv;
    pack_pair(hv, lv, v0, v1);
    *(uint32_t*)(H + idx) = hv;
    *(uint32_t*)(L + idx) = lv;
}

// ---------------- prep ----------------
__global__ void conv_split(const float* __restrict__ in, __nv_bfloat16* __restrict__ hi,
                           __nv_bfloat16* __restrict__ lo, int n4)
{
    int i = blockIdx.x * blockDim.x + threadIdx.x;
    if (i >= n4) return;
    float4 v = ((const float4*)in)[i];
    uint32_t h0, h1, l0, l1;
    pack_pair(h0, l0, v.x, v.y);
    pack_pair(h1, l1, v.z, v.w);
    ((uint32_t*)hi)[2 * i] = h0; ((uint32_t*)hi)[2 * i + 1] = h1;
    ((uint32_t*)lo)[2 * i] = l0; ((uint32_t*)lo)[2 * i + 1] = l1;
}
__global__ void conv_wqkv(const float* __restrict__ wq, const float* __restrict__ wk,
                          const float* __restrict__ wv)
{
    int id = blockIdx.x * 256 + threadIdx.x;
    if (id >= 3 * Dm * Dm) return;
    int n = id >> 10, d = id & 1023;
    int proj = n >> 10, nl = n & 1023, h = nl >> 6, e = nl & 63;
    const float* W = (proj == 0 ? wq : proj == 1 ? wk : wv);
    float v = W[((size_t)h * Dm + d) * Dh + e];
    __nv_bfloat16 hh = __float2bfloat16(v);
    g_wh[id] = hh;
    g_wl[id] = __float2bfloat16(v - __bfloat162float(hh));
}
__global__ void conv_wo(const float* __restrict__ wo)
{
    int id = blockIdx.x * 256 + threadIdx.x;
    if (id >= Dm * Dm) return;
    int n = id >> 10, k = id & 1023;
    float v = wo[(size_t)k * Dm + n];
    __nv_bfloat16 hh = __float2bfloat16(v);
    g_oh[id] = hh;
    g_ol[id] = __float2bfloat16(v - __bfloat162float(hh));
}

// ---- bf16x3 HMMA GEMM: 3-stage cp.async pipeline, 1 sync/slab, 2 CTAs/SM ---
#define ARR_BYTES 8192
#define BUF_BYTES (4 * ARR_BYTES)
#define GEMM_SMEM (3 * BUF_BYTES)      /* 98304 */

__global__ __launch_bounds__(256, 2) void hmma_gemm(
    const __nv_bfloat16* __restrict__ Ah, const __nv_bfloat16* __restrict__ Al,
    const __nv_bfloat16* __restrict__ Bh, const __nv_bfloat16* __restrict__ Bl,
    const float* __restrict__ b0, const float* __restrict__ b1,
    const float* __restrict__ b2, float* __restrict__ C, int mode)
{
    extern __shared__ char smc[];
    const uint32_t sb = smem_u32(smc);
    const int tid = threadIdx.x, wid = tid >> 5, lane = tid & 31;
    const int warp_m = wid >> 2, warp_n = wid & 3;
    const int g = lane >> 3, r = lane & 7;
    const int m0  = blockIdx.x * 128;
    const int n0g = blockIdx.y * 128;
    const int proj = n0g >> 10;
    const int nl   = n0g & 1023;
    const float* bias = (proj == 0 ? b0 : proj == 1 ? b1 : b2);

    const __nv_bfloat16* srcs[4];
    srcs[0] = Ah + (size_t)m0  * Dm;
    srcs[1] = Al + (size_t)m0  * Dm;
    srcs[2] = Bh + (size_t)n0g * Dm;
    srcs[3] = Bl + (size_t)n0g * Dm;

    const uint32_t aoff0 = (uint32_t)(((warp_m * 8 + (g & 1)) * 4 + (g >> 1)) * 128 + r * 16);
    const uint32_t boff0 = (uint32_t)(((warp_n * 4 + (g >> 1)) * 4 + (g & 1)) * 128 + r * 16);

    auto fill = [&](int buf, int k0) {
        #pragma unroll
        for (int arr = 0; arr < 4; arr++) {
            uint32_t abase = sb + buf * BUF_BYTES + arr * ARR_BYTES;
            const __nv_bfloat16* s = srcs[arr];
            #pragma unroll
            for (int i = 0; i < 2; i++) {
                int cid = tid + 256 * i;
                int row = cid >> 2, kc = (cid & 3) * 8;
                const void* gsrc = s + (size_t)row * Dm + k0 + kc;
                uint32_t soff = abase + (uint32_t)(((row >> 3) * 4 + (kc >> 3)) * 128
                                                   + (row & 7) * 16);
                CP_ASYNC16(soff, gsrc);
            }
        }
    };

    float acc[4][4][4];
    #pragma unroll
    for (int mi = 0; mi < 4; mi++)
        #pragma unroll
        for (int nj = 0; nj < 4; nj++)
            #pragma unroll
            for (int c = 0; c < 4; c++) acc[mi][nj][c] = 0.f;

    fill(0, 0);  CP_COMMIT();
    fill(1, 32); CP_COMMIT();

    const int NIT = Dm / 32;
    int buf = 0;
    for (int it = 0; it < NIT; it++) {
        if (it == NIT - 1) { CP_WAIT0(); } else { CP_WAIT1(); }
        __syncthreads();
        if (it + 2 < NIT) {
            int nb = buf + 2; if (nb >= 3) nb -= 3;
            fill(nb, (it + 2) * 32);
            CP_COMMIT();
        }

        const uint32_t bufb = sb + buf * BUF_BYTES;
        const uint32_t bAh = bufb, bAl = bufb + ARR_BYTES;
        const uint32_t bBh = bufb + 2 * ARR_BYTES, bBl = bufb + 3 * ARR_BYTES;

        #pragma unroll
        for (int ks = 0; ks < 2; ks++) {
            uint32_t afr[4][4];
            uint32_t bh[2][4], bl[2][4];
            ldmat4(bh[0], bBh + boff0 + ks * 256);
            ldmat4(bh[1], bBh + boff0 + 1024 + ks * 256);
            ldmat4(bl[0], bBl + boff0 + ks * 256);
            ldmat4(bl[1], bBl + boff0 + 1024 + ks * 256);
            #pragma unroll
            for (int mi = 0; mi < 4; mi++)
                ldmat4(afr[mi], bAh + aoff0 + mi * 1024 + ks * 256);
            #pragma unroll
            for (int mi = 0; mi < 4; mi++)
                #pragma unroll
                for (int nj = 0; nj < 4; nj++) {
                    mma16816(acc[mi][nj], afr[mi],
                             bh[nj >> 1][(nj & 1) * 2], bh[nj >> 1][(nj & 1) * 2 + 1]);
                    mma16816(acc[mi][nj], afr[mi],
                             bl[nj >> 1][(nj & 1) * 2], bl[nj >> 1][(nj & 1) * 2 + 1]);
                }
            #pragma unroll
            for (int mi = 0; mi < 4; mi++)
                ldmat4(afr[mi], bAl + aoff0 + mi * 1024 + ks * 256);
            #pragma unroll
            for (int mi = 0; mi < 4; mi++)
                #pragma unroll
                for (int nj = 0; nj < 4; nj++)
                    mma16816(acc[mi][nj], afr[mi],
                             bh[nj >> 1][(nj & 1) * 2], bh[nj >> 1][(nj & 1) * 2 + 1]);
        }
        if (++buf >= 3) buf = 0;
    }

    // epilogue
    const int gq = lane >> 2, tq = lane & 3;
    if (mode == 0) {
        #pragma unroll
        for (int mi = 0; mi < 4; mi++) {
            const int row = m0 + warp_m * 64 + mi * 16 + gq;
            #pragma unroll
            for (int nj = 0; nj < 4; nj++) {
                const int col = nl + warp_n * 32 + nj * 8 + tq * 2;
                const float bv0 = bias[col], bv1 = bias[col + 1];
                *(float2*)(C + (size_t)row * Dm + col) =
                    make_float2(acc[mi][nj][0] + bv0, acc[mi][nj][1] + bv1);
                *(float2*)(C + (size_t)(row + 8) * Dm + col) =
                    make_float2(acc[mi][nj][2] + bv0, acc[mi][nj][3] + bv1);
            }
        }
    } else {
        __nv_bfloat16* H = (proj == 0 ? g_qh : proj == 1 ? g_kh : g_vh);
        __nv_bfloat16* L = (proj == 0 ? g_ql : proj == 1 ? g_kl : g_vl);
        const float sc = (proj == 0) ? 0.125f : 1.f;
        #pragma unroll
        for (int mi = 0; mi < 4; mi++) {
            const size_t row = (size_t)(m0 + warp_m * 64 + mi * 16 + gq);
            #pragma unroll
            for (int nj = 0; nj < 4; nj++) {
                const int col = nl + warp_n * 32 + nj * 8 + tq * 2;
                const float bv0 = bias[col], bv1 = bias[col + 1];
                split_store(H, L, row * Dm + col,
                            (acc[mi][nj][0] + bv0) * sc, (acc[mi][nj][1] + bv1) * sc);
                split_store(H, L, (row + 8) * Dm + col,
                            (acc[mi][nj][2] + bv0) * sc, (acc[mi][nj][3] + bv1) * sc);
            }
        }
    }
}

// ---------------- HMMA flash attention (1 sync/kv-tile, heavy-first) --------
#define ATT_SMEM 65536
__device__ __forceinline__ uint32_t swo(int row, int e) {
    return (uint32_t)(((row >> 3) * 8 + (e >> 3)) * 128 + (((row & 7) ^ (e >> 3)) << 4));
}

__global__ __launch_bounds__(256) void fattn()
{
    extern __shared__ char sm[];
    const uint32_t sb = smem_u32(sm);
    const int tid = threadIdx.x, w = tid >> 5, lane = tid & 31;
    const int qb = gridDim.x - 1 - blockIdx.x;   // heavy tiles first
    const int h = blockIdx.y, b = blockIdx.z;
    const int q0 = qb * 128;
    const size_t tq0 = (size_t)b * Sq + q0;

    #pragma unroll
    for (int i = 0; i < 8; i++) {
        int sid = tid + 256 * i;
        int arr = sid >> 10, rc = sid & 1023, row = rc >> 3, c8 = rc & 7;
        const __nv_bfloat16* src = (arr ? g_ql : g_qh) + (tq0 + row) * Dm + h * 64 + c8 * 8;
        CP_ASYNC16(sb + arr * 16384 + (uint32_t)(((row >> 3) * 8 + c8) * 128
                   + (((row & 7) ^ c8) << 4)), src);
    }
    CP_COMMIT(); CP_WAIT0(); __syncthreads();

    uint32_t qh[4][4], ql[4][4];
    {
        int row = 16 * w + (lane & 7) + ((lane >> 3) & 1) * 8;
        #pragma unroll
        for (int ks = 0; ks < 4; ks++) {
            uint32_t off = swo(row, ks * 16 + (lane >> 4) * 8);
            ldmat4(qh[ks], sb + off);
            ldmat4(ql[ks], sb + 16384 + off);
        }
    }
    __syncthreads();

    float o[8][4], m[2] = {-1e30f, -1e30f}, l[2] = {0.f, 0.f};
    #pragma unroll
    for (int nj = 0; nj < 8; nj++)
        #pragma unroll
        for (int c = 0; c < 4; c++) o[nj][c] = 0.f;

    const int nkv = 2 * qb + 2;
    const size_t tb = (size_t)b * Sq;

    auto fillkv = [&](int st, int kt) {
        #pragma unroll
        for (int i = 0; i < 8; i++) {
            int sid = tid + 256 * i;
            int arr = sid >> 9, rc = sid & 511, row = rc >> 3, c8 = rc & 7;
            const __nv_bfloat16* s = (arr == 0 ? g_kh : arr == 1 ? g_kl :
                                      arr == 2 ? g_vh : g_vl);
            const __nv_bfloat16* src = s + (tb + kt * 64 + row) * Dm + h * 64 + c8 * 8;
            CP_ASYNC16(sb + st * 32768 + arr * 8192 + (uint32_t)(((row >> 3) * 8 + c8) * 128
                       + (((row & 7) ^ c8) << 4)), src);
        }
    };

    fillkv(0, 0); CP_COMMIT();

    for (int kt = 0; kt < nkv; kt++) {
        CP_WAIT0();
        __syncthreads();
        if (kt + 1 < nkv) { fillkv((kt + 1) & 1, kt + 1); CP_COMMIT(); }

        const uint32_t kbb = sb + (kt & 1) * 32768;
        float s[8][4];
        #pragma unroll
        for (int nj = 0; nj < 8; nj++)
            #pragma unroll
            for (int c = 0; c < 4; c++) s[nj][c] = 0.f;

        #pragma unroll
        for (int ks = 0; ks < 4; ks++) {
            #pragma unroll
            for (int njp = 0; njp < 4; njp++) {
                int krow = njp * 16 + (lane >> 4) * 8 + (lane & 7);
                uint32_t off = swo(krow, ks * 16 + ((lane >> 3) & 1) * 8);
                uint32_t kbh[4], kbl[4];
                ldmat4(kbh, kbb + off);
                ldmat4(kbl, kbb + 8192 + off);
                mma16816(s[2 * njp],     qh[ks], kbh[0], kbh[1]);
                mma16816(s[2 * njp + 1], qh[ks], kbh[2], kbh[3]);
                mma16816(s[2 * njp],     qh[ks], kbl[0], kbl[1]);
                mma16816(s[2 * njp + 1], qh[ks], kbl[2], kbl[3]);
                mma16816(s[2 * njp],     ql[ks], kbh[0], kbh[1]);
                mma16816(s[2 * njp + 1], ql[ks], kbh[2], kbh[3]);
            }
        }

        const int rowA = q0 + 16 * w + (lane >> 2);
        if (kt * 64 + 63 > q0 + 16 * w) {
            #pragma unroll
            for (int nj = 0; nj < 8; nj++)
                #pragma unroll
                for (int c = 0; c < 4; c++) {
                    int col = kt * 64 + nj * 8 + (lane & 3) * 2 + (c & 1);
                    if (col > rowA + (c >> 1) * 8) s[nj][c] = -1e30f;
                }
        }

        float mxA = -1e30f, mxB = -1e30f;
        #pragma unroll
        for (int nj = 0; nj < 8; nj++) {
            mxA = fmaxf(mxA, fmaxf(s[nj][0], s[nj][1]));
            mxB = fmaxf(mxB, fmaxf(s[nj][2], s[nj][3]));
        }
        #pragma unroll
        for (int off = 1; off < 4; off <<= 1) {
            mxA = fmaxf(mxA, __shfl_xor_sync(0xffffffffu, mxA, off));
            mxB = fmaxf(mxB, __shfl_xor_sync(0xffffffffu, mxB, off));
        }
        float mA = fmaxf(m[0], mxA), mB = fmaxf(m[1], mxB);
        float scA = fexp(m[0] - mA), scB = fexp(m[1] - mB);
        m[0] = mA; m[1] = mB;
        float sA = 0.f, sB = 0.f;
        #pragma unroll
        for (int nj = 0; nj < 8; nj++) {
            s[nj][0] = fexp(s[nj][0] - mA); s[nj][1] = fexp(s[nj][1] - mA);
            s[nj][2] = fexp(s[nj][2] - mB); s[nj][3] = fexp(s[nj][3] - mB);
            sA += s[nj][0] + s[nj][1];
            sB += s[nj][2] + s[nj][3];
        }
        #pragma unroll
        for (int off = 1; off < 4; off <<= 1) {
            sA += __shfl_xor_sync(0xffffffffu, sA, off);
            sB += __shfl_xor_sync(0xffffffffu, sB, off);
        }
        l[0] = l[0] * scA + sA;
        l[1] = l[1] * scB + sB;
        #pragma unroll
        for (int nj = 0; nj < 8; nj++) {
            o[nj][0] *= scA; o[nj][1] *= scA; o[nj][2] *= scB; o[nj][3] *= scB;
        }

        const uint32_t vbb = kbb + 16384;
        #pragma unroll
        for (int kk = 0; kk < 4; kk++) {
            uint32_t pah[4], pal[4];
            pack_pair(pah[0], pal[0], s[2 * kk][0],     s[2 * kk][1]);
            pack_pair(pah[1], pal[1], s[2 * kk][2],     s[2 * kk][3]);
            pack_pair(pah[2], pal[2], s[2 * kk + 1][0], s[2 * kk + 1][1]);
            pack_pair(pah[3], pal[3], s[2 * kk + 1][2], s[2 * kk + 1][3]);
            int vrow = kk * 16 + (lane & 7) + ((lane >> 3) & 1) * 8;
            #pragma unroll
            for (int ep = 0; ep < 4; ep++) {
                uint32_t off = swo(vrow, ep * 16 + (lane >> 4) * 8);
                uint32_t vbh[4], vbl[4];
                ldmat4t(vbh, vbb + off);
                ldmat4t(vbl, vbb + 8192 + off);
                mma16816(o[2 * ep],     pah, vbh[0], vbh[1]);
                mma16816(o[2 * ep + 1], pah, vbh[2], vbh[3]);
                mma16816(o[2 * ep],     pah, vbl[0], vbl[1]);
                mma16816(o[2 * ep + 1], pah, vbl[2], vbl[3]);
                mma16816(o[2 * ep],     pal, vbh[0], vbh[1]);
                mma16816(o[2 * ep + 1], pal, vbh[2], vbh[3]);
            }
        }
    }

    const float invA = 1.f / l[0], invB = 1.f / l[1];
    const size_t base = (tq0 + 16 * w + (lane >> 2)) * Dm + h * 64;
    #pragma unroll
    for (int nj = 0; nj < 8; nj++) {
        const int col = nj * 8 + (lane & 3) * 2;
        split_store(g_zh, g_zl, base + col,          o[nj][0] * invA, o[nj][1] * invA);
        split_store(g_zh, g_zl, base + 8 * Dm + col, o[nj][2] * invB, o[nj][3] * invB);
    }
}

// ---------------------------------------------------------------------------
extern "C" void kernel_launch(void* const* d_in, const int* in_sizes, int n_in,
                              void* d_out, int out_size)
{
    const float* x  = (const float*)d_in[0];
    const float* wq = (const float*)d_in[1];
    const float* bq = (const float*)d_in[2];
    const float* wk = (const float*)d_in[3];
    const float* bk = (const float*)d_in[4];
    const float* wv = (const float*)d_in[5];
    const float* bv = (const float*)d_in[6];
    const float* wo = (const float*)d_in[7];
    const float* bo = (const float*)d_in[8];
    float* out = (float*)d_out;

    cudaFuncSetAttribute(hmma_gemm, cudaFuncAttributeMaxDynamicSharedMemorySize, GEMM_SMEM);
    cudaFuncSetAttribute(fattn,     cudaFuncAttributeMaxDynamicSharedMemorySize, ATT_SMEM);

    void* p;
    cudaGetSymbolAddress(&p, g_xh); __nv_bfloat16* xh = (__nv_bfloat16*)p;
    cudaGetSymbolAddress(&p, g_xl); __nv_bfloat16* xl = (__nv_bfloat16*)p;
    cudaGetSymbolAddress(&p, g_zh); __nv_bfloat16* zh = (__nv_bfloat16*)p;
    cudaGetSymbolAddress(&p, g_zl); __nv_bfloat16* zl = (__nv_bfloat16*)p;
    cudaGetSymbolAddress(&p, g_wh); __nv_bfloat16* wh = (__nv_bfloat16*)p;
    cudaGetSymbolAddress(&p, g_wl); __nv_bfloat16* wl = (__nv_bfloat16*)p;
    cudaGetSymbolAddress(&p, g_oh); __nv_bfloat16* oh = (__nv_bfloat16*)p;
    cudaGetSymbolAddress(&p, g_ol); __nv_bfloat16* ol = (__nv_bfloat16*)p;

    conv_split<<<(Tt * Dm / 4 + 255) / 256, 256>>>(x, xh, xl, Tt * Dm / 4);
    conv_wqkv<<<(3 * Dm * Dm + 255) / 256, 256>>>(wq, wk, wv);
    conv_wo<<<(Dm * Dm + 255) / 256, 256>>>(wo);

    hmma_gemm<<<dim3(Tt / 128, 24), 256, GEMM_SMEM>>>(
        xh, xl, wh, wl, bq, bk, bv, nullptr, 1);

    fattn<<<dim3(Sq / 128, Hh, Bsz), 256, ATT_SMEM>>>();

    hmma_gemm<<<dim3(Tt / 128, 8), 256, GEMM_SMEM>>>(
        zh, zl, oh, ol, bo, bo, bo, out, 0);
}